// round 9
// baseline (speedup 1.0000x reference)
#include <cuda_runtime.h>
#include <math.h>

#define NN    10000
#define EE    160000
#define GG    128
#define HID   25
#define DOUT  32
#define BEPS  1e-5f
#define HP    32          // padded h row (floats)
#define TILE  136         // nodes per y tile
#define NTX   74          // node tiles  (74*136 >= NN)
#define NBLK  148
#define NTHR  256

typedef unsigned long long u64;

// ---------------- f32x2 helpers (bit-exact packed fp32 FMA) ------------------
__device__ __forceinline__ u64 pk2(float a, float b) {
    u64 r; asm("mov.b64 %0, {%1, %2};" : "=l"(r) : "f"(a), "f"(b)); return r;
}
__device__ __forceinline__ u64 fma2(u64 a, u64 b, u64 c) {
    u64 d; asm("fma.rn.f32x2 %0, %1, %2, %3;" : "=l"(d) : "l"(a), "l"(b), "l"(c)); return d;
}
__device__ __forceinline__ void upk2(u64 u, float& a, float& b) {
    asm("mov.b64 {%0, %1}, %2;" : "=f"(a), "=f"(b) : "l"(u));
}

// ---------------- scratch (zero-at-exit invariant for marked arrays) ---------
__device__ float  d_h0[(size_t)EE * HP];
__device__ float  d_h1[(size_t)EE * HP];
__device__ double d_mom[9];                     // zeroed at exit
__device__ float  d_wf[2][3][32];
__device__ float  d_bf[2][32];
__device__ float  d_y0[(size_t)NN * HID * DOUT];
__device__ float  d_y1[(size_t)NN * HID * DOUT];
__device__ float  d_xb[NN * DOUT];
__device__ float  d_agg[NN * DOUT];
__device__ float  d_x0[NN * DOUT];
__device__ float  d_deg[NN];                    // zeroed at exit
__device__ int    d_degs[NN];                   // zeroed at exit
__device__ int    d_start[NN + 1];
__device__ int    d_cursor[NN];
__device__ int    d_perm[EE];
__device__ int    d_dsts[EE];
__device__ float  d_gsum[GG * DOUT];            // zeroed at exit
__device__ float  d_gcnt[GG];                   // zeroed at exit

// ---------------- software grid barrier --------------------------------------
__device__ int           bar_count = 0;
__device__ volatile int  bar_gen   = 0;

__device__ __forceinline__ void gsync() {
    __threadfence();
    __syncthreads();
    if (threadIdx.x == 0) {
        int g = bar_gen;
        if (atomicAdd(&bar_count, 1) == (int)gridDim.x - 1) {
            bar_count = 0;
            __threadfence();
            bar_gen = g + 1;
        } else {
            while (bar_gen == g) __nanosleep(64);
        }
    }
    __syncthreads();
    __threadfence();
}

// ---------------- phase helpers ----------------------------------------------
// y[n][k][o] = sum_i x[n][i] * w2[k][i][o]; aux plane (ky==HID): xb + zero agg
template <int DIN>
__device__ __forceinline__ void y_phase(char* smc, const float* __restrict__ xin,
                                        const float* __restrict__ w2,
                                        const float* __restrict__ b2,
                                        float* __restrict__ yout,
                                        int vstart, int vstride) {
    float (*xs)[TILE] = (float (*)[TILE])smc;
    const int tid = threadIdx.x, lane = tid & 31, w = tid >> 5;
    for (int vt = vstart; vt < NTX * (HID + 1); vt += vstride) {
        int kx = vt % NTX;
        int ky = vt / NTX;
        int nbeg = kx * TILE;
        for (int idx = tid; idx < TILE * DIN; idx += NTHR) {
            int t = idx / DIN, i = idx % DIN;
            int n = nbeg + t;
            xs[i][t] = (n < NN) ? xin[(size_t)n * DIN + i] : 0.f;
        }
        __syncthreads();
        float wreg[DIN];
        if (ky < HID) {
#pragma unroll
            for (int i = 0; i < DIN; i++)
                wreg[i] = __ldg(&w2[(ky * DIN + i) * DOUT + lane]);
            for (int p = w; p < TILE / 2; p += 8) {
                u64 acc = 0;
#pragma unroll
                for (int i = 0; i < DIN; i++) {
                    u64 xv = *(const u64*)&xs[i][2 * p];
                    acc = fma2(xv, pk2(wreg[i], wreg[i]), acc);
                }
                float va, vb; upk2(acc, va, vb);
                int n = nbeg + 2 * p;
                if (n < NN)     yout[((size_t)n * HID + ky) * DOUT + lane] = va;
                if (n + 1 < NN) yout[((size_t)(n + 1) * HID + ky) * DOUT + lane] = vb;
            }
        } else {
#pragma unroll
            for (int i = 0; i < DIN; i++)
                wreg[i] = __ldg(&b2[i * DOUT + lane]);
            for (int p = w; p < TILE / 2; p += 8) {
                u64 acc = 0;
#pragma unroll
                for (int i = 0; i < DIN; i++) {
                    u64 xv = *(const u64*)&xs[i][2 * p];
                    acc = fma2(xv, pk2(wreg[i], wreg[i]), acc);
                }
                float va, vb; upk2(acc, va, vb);
                int n = nbeg + 2 * p;
                if (n < NN)     { d_xb[n * DOUT + lane] = va;
                                  d_agg[n * DOUT + lane] = 0.f; }
                if (n + 1 < NN) { d_xb[(n + 1) * DOUT + lane] = vb;
                                  d_agg[(n + 1) * DOUT + lane] = 0.f; }
            }
        }
        __syncthreads();
    }
}

// normalized h (BN+relu folded) for both layers, coalesced padded stores
__device__ __forceinline__ void h_phase(char* smc, const float* __restrict__ ea,
                                        int cstart, int cstride) {
    float* sst = (float*)smc;                        // 256*(HP+1) floats
    const int tid = threadIdx.x;
    for (int c = cstart; c < EE / 256; c += cstride) {
        int e = c * 256 + tid;
        size_t base = (size_t)c * 256 * HP;
        float a0 = ea[3 * e + 0], a1 = ea[3 * e + 1], a2 = ea[3 * e + 2];
#pragma unroll
        for (int l = 0; l < 2; l++) {
            float h[HID];
#pragma unroll
            for (int k = 0; k < HID; k++)
                h[k] = fmaxf(
                    fmaf(a0, d_wf[l][0][k],
                    fmaf(a1, d_wf[l][1][k],
                    fmaf(a2, d_wf[l][2][k], d_bf[l][k]))), 0.f);
#pragma unroll
            for (int k = 0; k < HID; k++) sst[tid * (HP + 1) + k] = h[k];
            __syncthreads();
            float* dst = l ? d_h1 : d_h0;
            for (int i = tid; i < 256 * HP; i += 256) {
                int col = i & 31;
                dst[base + i] = (col < HID) ? sst[(i >> 5) * (HP + 1) + col] : 0.f;
            }
            __syncthreads();
        }
    }
}

// messages: warp per source node, smem-broadcast h pairs, fma2
__device__ __forceinline__ void msg_phase(char* smc, const float* __restrict__ hbuf,
                                          const float* __restrict__ ybuf) {
    float (*sw)[2][32] = (float (*)[2][32])smc;
    const int wip  = threadIdx.x >> 5;
    const int lane = threadIdx.x & 31;
    for (int s = blockIdx.x * 8 + wip; s < NN; s += NBLK * 8) {
        int beg = d_start[s], end = d_start[s + 1];
        if (beg == end) continue;
        float xb = d_xb[s * DOUT + lane];
        const float* yrow = ybuf + (size_t)s * HID * DOUT;
        u64 yp[12]; float y24;
#pragma unroll
        for (int k = 0; k < 12; k++)
            yp[k] = pk2(yrow[(2 * k) * DOUT + lane], yrow[(2 * k + 1) * DOUT + lane]);
        y24 = yrow[24 * DOUT + lane];

        int   e0       = d_perm[beg];
        float hv_next  = hbuf[(size_t)e0 * HP + lane];
        int   dst_next = d_dsts[beg];
        for (int p = beg; p < end; p++) {
            int buf = p & 1;
            sw[wip][buf][lane] = hv_next;
            int dst = dst_next;
            if (p + 1 < end) {
                int e2   = d_perm[p + 1];
                hv_next  = hbuf[(size_t)e2 * HP + lane];
                dst_next = d_dsts[p + 1];
            }
            __syncwarp();
            const u64* hp = (const u64*)sw[wip][buf];
            u64 acc = 0;
#pragma unroll
            for (int k = 0; k < 12; k++) acc = fma2(hp[k], yp[k], acc);
            float ma, mb; upk2(acc, ma, mb);
            float m = fmaf(sw[wip][buf][24], y24, xb + ma + mb);
            atomicAdd(&d_agg[dst * DOUT + lane], m);
        }
    }
}

// node update (+ pooling on last layer)
template <int DIN>
__device__ __forceinline__ void x_phase(const float* __restrict__ xin,
                                        const float* __restrict__ wr,
                                        const float* __restrict__ bc,
                                        const int* __restrict__ batch, int last) {
    for (int idx = blockIdx.x * NTHR + threadIdx.x; idx < NN * DOUT; idx += NBLK * NTHR) {
        int n = idx / DOUT, o = idx % DOUT;
        float root = __ldg(&bc[o]);
#pragma unroll
        for (int i = 0; i < DIN; i++)
            root = fmaf(xin[(size_t)n * DIN + i], __ldg(&wr[i * DOUT + o]), root);
        float dg = fmaxf(d_deg[n], 1.f);
        float v = d_agg[idx] / dg + root;
        v = (v > 0.f) ? v : expm1f(v);
        if (last) atomicAdd(&d_gsum[batch[n] * DOUT + o], v);
        else      d_x0[idx] = v;
    }
}

// ---------------- the single persistent kernel -------------------------------
__global__ void __launch_bounds__(NTHR, 1)
k_all(const float* __restrict__ x,   const float* __restrict__ ea,
      const int*   __restrict__ ei,  const int*   __restrict__ batch,
      const float* __restrict__ w1_0, const float* __restrict__ b1_0,
      const float* __restrict__ g_0,  const float* __restrict__ be_0,
      const float* __restrict__ w2_0, const float* __restrict__ b2_0,
      const float* __restrict__ wr_0, const float* __restrict__ bc_0,
      const float* __restrict__ w1_1, const float* __restrict__ b1_1,
      const float* __restrict__ g_1,  const float* __restrict__ be_1,
      const float* __restrict__ w2_1, const float* __restrict__ b2_1,
      const float* __restrict__ wr_1, const float* __restrict__ bc_1,
      const float* __restrict__ wfc,  const float* __restrict__ bfc,
      float* __restrict__ out) {
    __shared__ __align__(16) char smb[256 * (HP + 1) * 4];   // 33792 B, reused per phase
    const int bid = blockIdx.x, tid = threadIdx.x;

    // ======== P1: moments | src-deg | dst-deg + graph counts ========
    if (bid < 48) {
        float m[9] = {0.f, 0.f, 0.f, 0.f, 0.f, 0.f, 0.f, 0.f, 0.f};
        for (int t = bid * NTHR + tid; t < EE / 4; t += 48 * NTHR) {
            const float4* p = (const float4*)(ea + t * 12);
            float4 A = p[0], B = p[1], C = p[2];
            float ax[4] = {A.x, A.w, B.z, C.y};
            float ay[4] = {A.y, B.x, B.w, C.z};
            float az[4] = {A.z, B.y, C.x, C.w};
#pragma unroll
            for (int j = 0; j < 4; j++) {
                float a0 = ax[j], a1 = ay[j], a2 = az[j];
                m[0] += a0; m[1] += a1; m[2] += a2;
                m[3] = fmaf(a0, a0, m[3]); m[4] = fmaf(a0, a1, m[4]);
                m[5] = fmaf(a0, a2, m[5]); m[6] = fmaf(a1, a1, m[6]);
                m[7] = fmaf(a1, a2, m[7]); m[8] = fmaf(a2, a2, m[8]);
            }
        }
        float* smom = (float*)smb;
        int lane = tid & 31, w = tid >> 5;
#pragma unroll
        for (int j = 0; j < 9; j++) {
            float v = m[j];
#pragma unroll
            for (int off = 16; off; off >>= 1) v += __shfl_down_sync(0xffffffffu, v, off);
            if (lane == 0) smom[j * 8 + w] = v;
        }
        __syncthreads();
        if (tid < 9) {
            float s = 0.f;
#pragma unroll
            for (int j = 0; j < 8; j++) s += smom[tid * 8 + j];
            atomicAdd(&d_mom[tid], (double)s);
        }
    } else if (bid < 96) {
        for (int t = (bid - 48) * NTHR + tid; t < EE / 4; t += 48 * NTHR) {
            int4 s4 = ((const int4*)ei)[t];
            atomicAdd(&d_degs[s4.x], 1);
            atomicAdd(&d_degs[s4.y], 1);
            atomicAdd(&d_degs[s4.z], 1);
            atomicAdd(&d_degs[s4.w], 1);
        }
    } else {
        for (int t = (bid - 96) * NTHR + tid; t < EE / 4; t += 52 * NTHR) {
            int4 t4 = ((const int4*)(ei + EE))[t];
            atomicAdd(&d_deg[t4.x], 1.f);
            atomicAdd(&d_deg[t4.y], 1.f);
            atomicAdd(&d_deg[t4.z], 1.f);
            atomicAdd(&d_deg[t4.w], 1.f);
        }
        for (int n = (bid - 96) * NTHR + tid; n < NN; n += 52 * NTHR)
            atomicAdd(&d_gcnt[batch[n]], 1.f);
    }
    gsync();

    // ======== P2: scan | BN fold | y16 ========
    if (bid == 0) {
        int* s = (int*)smb;
        const int CH = (NN + NTHR - 1) / NTHR;               // 40
        int loc[CH];
        int base = tid * CH;
        int run = 0;
#pragma unroll
        for (int i = 0; i < CH; i++) {
            int v = (base + i < NN) ? d_degs[base + i] : 0;
            loc[i] = run; run += v;
        }
        s[tid] = run;
        __syncthreads();
        for (int off = 1; off < NTHR; off <<= 1) {
            int v = (tid >= off) ? s[tid - off] : 0;
            __syncthreads();
            s[tid] += v;
            __syncthreads();
        }
        int excl = tid ? s[tid - 1] : 0;
#pragma unroll
        for (int i = 0; i < CH; i++)
            if (base + i < NN) {
                int v = excl + loc[i];
                d_start[base + i]  = v;
                d_cursor[base + i] = v;
            }
        if (tid == NTHR - 1) d_start[NN] = s[NTHR - 1];
    } else if (bid == 1) {
        int layer = tid >> 5, k = tid & 31;
        if (layer < 2 && k < HID) {
            const float* w1 = layer ? w1_1 : w1_0;
            const float* b1 = layer ? b1_1 : b1_0;
            const float* g  = layer ? g_1  : g_0;
            const float* be = layer ? be_1 : be_0;
            double wa = w1[k], wb = w1[HID + k], wc = w1[2 * HID + k], b = b1[k];
            double S0 = d_mom[0], S1 = d_mom[1], S2 = d_mom[2];
            double M00 = d_mom[3], M01 = d_mom[4], M02 = d_mom[5];
            double M11 = d_mom[6], M12 = d_mom[7], M22 = d_mom[8];
            double lin = S0 * wa + S1 * wb + S2 * wc;
            double mu  = (lin + (double)EE * b) / (double)EE;
            double sq  = wa * wa * M00 + M11 * wb * wb + M22 * wc * wc
                       + 2.0 * (wa * wb * M01 + wa * wc * M02 + wb * wc * M12)
                       + 2.0 * b * lin + (double)EE * b * b;
            double var = sq / (double)EE - mu * mu;
            float rs = rsqrtf((float)var + BEPS);
            float sc = rs * g[k];
            float sh = be[k] - (float)mu * sc;
            d_wf[layer][0][k] = (float)wa * sc;
            d_wf[layer][1][k] = (float)wb * sc;
            d_wf[layer][2][k] = (float)wc * sc;
            d_bf[layer][k]    = (float)b * sc + sh;
        }
    } else {
        y_phase<16>(smb, x, w2_0, b2_0, d_y0, bid - 2, NBLK - 2);
    }
    gsync();

    // ======== P3: scatter | normalized h both layers ========
    if (bid < 48) {
        for (int t = bid * NTHR + tid; t < EE / 4; t += 48 * NTHR) {
            int4 s4 = ((const int4*)ei)[t];
            int4 t4 = ((const int4*)(ei + EE))[t];
            int i = t * 4;
            int p0 = atomicAdd(&d_cursor[s4.x], 1);
            int p1 = atomicAdd(&d_cursor[s4.y], 1);
            int p2 = atomicAdd(&d_cursor[s4.z], 1);
            int p3 = atomicAdd(&d_cursor[s4.w], 1);
            d_perm[p0] = i;     d_dsts[p0] = t4.x;
            d_perm[p1] = i + 1; d_dsts[p1] = t4.y;
            d_perm[p2] = i + 2; d_dsts[p2] = t4.z;
            d_perm[p3] = i + 3; d_dsts[p3] = t4.w;
        }
    } else {
        h_phase(smb, ea, bid - 48, NBLK - 48);
    }
    gsync();

    // ======== P4: layer-0 messages ========
    msg_phase(smb, d_h0, d_y0);
    gsync();

    // ======== P5: layer-0 node update ========
    x_phase<16>(x, wr_0, bc_0, batch, 0);
    gsync();

    // ======== P6: y32 ========
    y_phase<32>(smb, d_x0, w2_1, b2_1, d_y1, bid, NBLK);
    gsync();

    // ======== P7: layer-1 messages ========
    msg_phase(smb, d_h1, d_y1);
    gsync();

    // ======== P8: layer-1 node update + pooling ========
    x_phase<32>(d_x0, wr_1, bc_1, batch, 1);
    gsync();

    // ======== P9: fc + re-zero counters for next replay ========
    if (bid == 0) {
        if (tid < GG) {
            float c = fmaxf(d_gcnt[tid], 1.f);
            float acc = 0.f;
#pragma unroll
            for (int o = 0; o < DOUT; o++)
                acc = fmaf(d_gsum[tid * DOUT + o] / c, __ldg(&wfc[o]), acc);
            out[tid] = acc + bfc[0];
        }
        __syncthreads();
        for (int i = tid; i < GG * DOUT; i += NTHR) d_gsum[i] = 0.f;
        if (tid < GG) d_gcnt[tid] = 0.f;
    } else {
        for (int i = (bid - 1) * NTHR + tid; i < NN; i += (NBLK - 1) * NTHR) {
            d_degs[i] = 0;
            d_deg[i]  = 0.f;
        }
        if (bid == 1 && tid < 9) d_mom[tid] = 0.0;
    }
}

// ---------------- launch -----------------------------------------------------
extern "C" void kernel_launch(void* const* d_in, const int* in_sizes, int n_in,
                              void* d_out, int out_size) {
    (void)in_sizes; (void)n_in; (void)out_size;
    k_all<<<NBLK, NTHR>>>(
        (const float*)d_in[0],  (const float*)d_in[1],
        (const int*)d_in[2],    (const int*)d_in[3],
        (const float*)d_in[4],  (const float*)d_in[5],
        (const float*)d_in[6],  (const float*)d_in[7],
        (const float*)d_in[8],  (const float*)d_in[9],
        (const float*)d_in[10], (const float*)d_in[11],
        (const float*)d_in[12], (const float*)d_in[13],
        (const float*)d_in[14], (const float*)d_in[15],
        (const float*)d_in[16], (const float*)d_in[17],
        (const float*)d_in[18], (const float*)d_in[19],
        (const float*)d_in[20], (const float*)d_in[21],
        (float*)d_out);
}

// round 11
// speedup vs baseline: 2.3556x; 2.3556x over previous
#include <cuda_runtime.h>
#include <math.h>

#define NN   10000
#define EE   160000
#define GG   128
#define HID  25
#define DOUT 32
#define BEPS 1e-5f
#define NX   74          // node-tile blocks in k_y
#define TILE 136         // ceil(NN/NX), even

typedef unsigned long long u64;

// ---------------- f32x2 helpers (bit-exact packed fp32 FMA) ------------------
__device__ __forceinline__ u64 pk2(float a, float b) {
    u64 r; asm("mov.b64 %0, {%1, %2};" : "=l"(r) : "f"(a), "f"(b)); return r;
}
__device__ __forceinline__ u64 fma2(u64 a, u64 b, u64 c) {
    u64 d; asm("fma.rn.f32x2 %0, %1, %2, %3;" : "=l"(d) : "l"(a), "l"(b), "l"(c)); return d;
}
__device__ __forceinline__ void upk2(u64 u, float& a, float& b) {
    asm("mov.b64 {%0, %1}, %2;" : "=f"(a), "=f"(b) : "l"(u));
}

// ---------------- scratch ----------------------------------------------------
__device__ double d_mom[9];                     // S0,S1,S2,M00,M01,M02,M11,M12,M22
__device__ float  d_wf[2][3][32];               // BN-folded first-linear weights
__device__ float  d_bf[2][32];                  // BN-folded bias
__device__ float  d_y[(size_t)NN * HID * DOUT]; // y[n][k][o]
__device__ float  d_xb[NN * DOUT];
__device__ float  d_agg[NN * DOUT];
__device__ float  d_x0[NN * DOUT];
__device__ float  d_deg[NN];                    // dst in-degree
__device__ int    d_degs[NN];                   // src out-degree
__device__ int    d_start[NN + 1];
__device__ int    d_cursor[NN];
__device__ int    d_perm[EE];                   // sorted pos -> original edge id
__device__ int    d_dsts[EE];
__device__ float  d_gsum[GG * DOUT];
__device__ float  d_gcnt[GG];

// ---------------- default stream: CSR prologue -------------------------------
// 4 edges per thread, int4 loads (EE % 4 == 0)
__global__ void k_deg_src(const int* __restrict__ ei) {
    int i = (blockIdx.x * blockDim.x + threadIdx.x) * 4;
    if (i < EE) {
        int4 s = *(const int4*)(ei + i);
        atomicAdd(&d_degs[s.x], 1);
        atomicAdd(&d_degs[s.y], 1);
        atomicAdd(&d_degs[s.z], 1);
        atomicAdd(&d_degs[s.w], 1);
    }
}

__global__ void k_scan() {
    __shared__ int s[1024];
    const int t = threadIdx.x;
    const int CH = (NN + 1023) / 1024;
    int loc[CH];
    int base = t * CH;
    int run = 0;
#pragma unroll
    for (int i = 0; i < CH; i++) {
        int v = (base + i < NN) ? d_degs[base + i] : 0;
        loc[i] = run; run += v;
    }
    s[t] = run;
    __syncthreads();
    for (int off = 1; off < 1024; off <<= 1) {
        int v = (t >= off) ? s[t - off] : 0;
        __syncthreads();
        s[t] += v;
        __syncthreads();
    }
    int excl = (t > 0) ? s[t - 1] : 0;
#pragma unroll
    for (int i = 0; i < CH; i++)
        if (base + i < NN) {
            int v = excl + loc[i];
            d_start[base + i]  = v;
            d_cursor[base + i] = v;
        }
    if (t == 1023) d_start[NN] = s[1023];
}

__global__ void k_scatter(const int* __restrict__ ei) {
    int i = (blockIdx.x * blockDim.x + threadIdx.x) * 4;
    if (i < EE) {
        int4 s = *(const int4*)(ei + i);
        int4 t = *(const int4*)(ei + EE + i);
        int p0 = atomicAdd(&d_cursor[s.x], 1);
        int p1 = atomicAdd(&d_cursor[s.y], 1);
        int p2 = atomicAdd(&d_cursor[s.z], 1);
        int p3 = atomicAdd(&d_cursor[s.w], 1);
        d_perm[p0] = i;     d_dsts[p0] = t.x;
        d_perm[p1] = i + 1; d_dsts[p1] = t.y;
        d_perm[p2] = i + 2; d_dsts[p2] = t.z;
        d_perm[p3] = i + 3; d_dsts[p3] = t.w;
    }
}

// ---------------- stream s2: dst degree + graph counts -----------------------
__global__ void k_deg_dst(const int* __restrict__ ei, const int* __restrict__ batch) {
    int tid = blockIdx.x * blockDim.x + threadIdx.x;
    int i = tid * 4;
    if (i < EE) {
        int4 t = *(const int4*)(ei + EE + i);
        atomicAdd(&d_deg[t.x], 1.f);
        atomicAdd(&d_deg[t.y], 1.f);
        atomicAdd(&d_deg[t.z], 1.f);
        atomicAdd(&d_deg[t.w], 1.f);
    }
    if (tid < NN) atomicAdd(&d_gcnt[batch[tid]], 1.f);
}

// ---------------- stream s1: edge-attr moments (4 edges/thread) --------------
__global__ void k_mom(const float* __restrict__ ea) {
    __shared__ float smom[9 * 8];
    const int tid = threadIdx.x;
    const int t = blockIdx.x * 256 + tid;
    float m[9] = {0.f, 0.f, 0.f, 0.f, 0.f, 0.f, 0.f, 0.f, 0.f};
    int base = t * 12;
    if (base < EE * 3) {
        const float4* p = (const float4*)(ea + base);
        float4 A = p[0], B = p[1], C = p[2];
        float ax[4] = {A.x, A.w, B.z, C.y};
        float ay[4] = {A.y, B.x, B.w, C.z};
        float az[4] = {A.z, B.y, C.x, C.w};
#pragma unroll
        for (int j = 0; j < 4; j++) {
            float a0 = ax[j], a1 = ay[j], a2 = az[j];
            m[0] += a0; m[1] += a1; m[2] += a2;
            m[3] = fmaf(a0, a0, m[3]); m[4] = fmaf(a0, a1, m[4]);
            m[5] = fmaf(a0, a2, m[5]); m[6] = fmaf(a1, a1, m[6]);
            m[7] = fmaf(a1, a2, m[7]); m[8] = fmaf(a2, a2, m[8]);
        }
    }
    int lane = tid & 31, w = tid >> 5;
#pragma unroll
    for (int j = 0; j < 9; j++) {
        float v = m[j];
#pragma unroll
        for (int off = 16; off; off >>= 1) v += __shfl_down_sync(0xffffffffu, v, off);
        if (lane == 0) smom[j * 8 + w] = v;
    }
    __syncthreads();
    if (tid < 9) {
        float s = 0.f;
#pragma unroll
        for (int j = 0; j < 8; j++) s += smom[tid * 8 + j];
        atomicAdd(&d_mom[tid], (double)s);
    }
}

// BN fold from moments -> folded first-linear weights (both layers)
__global__ void k_bn_both(const float* __restrict__ g0, const float* __restrict__ be0,
                          const float* __restrict__ g1, const float* __restrict__ be1,
                          const float* __restrict__ w1a, const float* __restrict__ b1a,
                          const float* __restrict__ w1b, const float* __restrict__ b1b) {
    int t = threadIdx.x;
    int layer = t >> 5, k = t & 31;
    if (layer < 2 && k < HID) {
        const float* w1 = layer ? w1b : w1a;
        const float* b1 = layer ? b1b : b1a;
        const float* g  = layer ? g1  : g0;
        const float* be = layer ? be1 : be0;
        double wa = w1[k], wb = w1[HID + k], wc = w1[2 * HID + k], b = b1[k];
        double S0 = d_mom[0], S1 = d_mom[1], S2 = d_mom[2];
        double M00 = d_mom[3], M01 = d_mom[4], M02 = d_mom[5];
        double M11 = d_mom[6], M12 = d_mom[7], M22 = d_mom[8];
        double lin = S0 * wa + S1 * wb + S2 * wc;
        double mu  = (lin + (double)EE * b) / (double)EE;
        double sq  = wa * wa * M00 + M11 * wb * wb + M22 * wc * wc
                   + 2.0 * (wa * wb * M01 + wa * wc * M02 + wb * wc * M12)
                   + 2.0 * b * lin + (double)EE * b * b;
        double var = sq / (double)EE - mu * mu;
        float rs = rsqrtf((float)var + BEPS);
        float sc = rs * g[k];
        float sh = be[k] - (float)mu * sc;
        d_wf[layer][0][k] = (float)wa * sc;
        d_wf[layer][1][k] = (float)wb * sc;
        d_wf[layer][2][k] = (float)wc * sc;
        d_bf[layer][k]    = (float)b * sc + sh;
    }
}

// ---------------- per-node y[n,k,o] + xb, zero agg ---------------------------
template <int DIN>
__global__ void k_y(const float* __restrict__ xin_ext, int use_ext,
                    const float* __restrict__ w2, const float* __restrict__ b2) {
    __shared__ __align__(16) float xs[DIN][TILE];
    const float* xin = use_ext ? xin_ext : d_x0;
    const int tid = threadIdx.x, lane = tid & 31, w = tid >> 5;
    const int k = blockIdx.y;
    const int nbeg = blockIdx.x * TILE;

    for (int idx = tid; idx < TILE * DIN; idx += 128) {
        int t = idx / DIN, i = idx % DIN;
        int n = nbeg + t;
        xs[i][t] = (n < NN) ? xin[(size_t)n * DIN + i] : 0.f;
    }
    __syncthreads();

    float wreg[DIN];
    if (k < HID) {
#pragma unroll
        for (int i = 0; i < DIN; i++)
            wreg[i] = __ldg(&w2[(k * DIN + i) * DOUT + lane]);
        for (int p = w; p < TILE / 2; p += 4) {
            u64 acc = 0;
#pragma unroll
            for (int i = 0; i < DIN; i++) {
                u64 xv = *(const u64*)&xs[i][2 * p];
                acc = fma2(xv, pk2(wreg[i], wreg[i]), acc);
            }
            float va, vb; upk2(acc, va, vb);
            int n = nbeg + 2 * p;
            if (n < NN)     d_y[((size_t)n * HID + k) * DOUT + lane] = va;
            if (n + 1 < NN) d_y[((size_t)(n + 1) * HID + k) * DOUT + lane] = vb;
        }
    } else {
#pragma unroll
        for (int i = 0; i < DIN; i++)
            wreg[i] = __ldg(&b2[i * DOUT + lane]);
        for (int p = w; p < TILE / 2; p += 4) {
            u64 acc = 0;
#pragma unroll
            for (int i = 0; i < DIN; i++) {
                u64 xv = *(const u64*)&xs[i][2 * p];
                acc = fma2(xv, pk2(wreg[i], wreg[i]), acc);
            }
            float va, vb; upk2(acc, va, vb);
            int n = nbeg + 2 * p;
            if (n < NN)     { d_xb[n * DOUT + lane] = va;
                              d_agg[n * DOUT + lane] = 0.f; }
            if (n + 1 < NN) { d_xb[(n + 1) * DOUT + lane] = vb;
                              d_agg[(n + 1) * DOUT + lane] = 0.f; }
        }
    }
}

// ---------------- messages: warp/src, INLINE h, smem-broadcast pairs ---------
__global__ void k_msg(const float* __restrict__ ea, int layer) {
    __shared__ __align__(16) float sw[8][2][32];
    __shared__ float swf0[32], swf1[32], swf2[32], sbf[32];
    const int wip  = threadIdx.x >> 5;
    const int gw   = (blockIdx.x * blockDim.x + threadIdx.x) >> 5;
    const int lane = threadIdx.x & 31;
    if (threadIdx.x < 32) {
        swf0[threadIdx.x] = d_wf[layer][0][threadIdx.x];
        swf1[threadIdx.x] = d_wf[layer][1][threadIdx.x];
        swf2[threadIdx.x] = d_wf[layer][2][threadIdx.x];
        sbf[threadIdx.x]  = d_bf[layer][threadIdx.x];
    }
    __syncthreads();
    if (gw >= NN) return;
    int beg = d_start[gw], end = d_start[gw + 1];
    if (beg == end) return;

    const float wf0 = swf0[lane], wf1 = swf1[lane], wf2 = swf2[lane], bf = sbf[lane];
    float xb = d_xb[gw * DOUT + lane];
    const float* yrow = d_y + (size_t)gw * HID * DOUT;
    u64 yp[12]; float y24;
#pragma unroll
    for (int k = 0; k < 12; k++)
        yp[k] = pk2(yrow[(2 * k) * DOUT + lane], yrow[(2 * k + 1) * DOUT + lane]);
    y24 = yrow[24 * DOUT + lane];

    // prefetch edge 0: its attrs (12B broadcast) + dst
    int   e0 = d_perm[beg];
    float a0n = __ldg(&ea[3 * e0]), a1n = __ldg(&ea[3 * e0 + 1]), a2n = __ldg(&ea[3 * e0 + 2]);
    int   dst_next = d_dsts[beg];

    for (int p = beg; p < end; p++) {
        // inline BN-folded first linear + relu (3 FMA per lane)
        float hv = fmaxf(fmaf(a0n, wf0, fmaf(a1n, wf1, fmaf(a2n, wf2, bf))), 0.f);
        int buf = p & 1;
        sw[wip][buf][lane] = hv;
        int dst = dst_next;
        if (p + 1 < end) {
            int e2 = d_perm[p + 1];
            a0n = __ldg(&ea[3 * e2]);
            a1n = __ldg(&ea[3 * e2 + 1]);
            a2n = __ldg(&ea[3 * e2 + 2]);
            dst_next = d_dsts[p + 1];
        }
        __syncwarp();
        const u64* hp = (const u64*)sw[wip][buf];       // lanes 0..23 as 12 pairs
        u64 acc = 0;
#pragma unroll
        for (int k = 0; k < 12; k++) acc = fma2(hp[k], yp[k], acc);
        float ma, mb; upk2(acc, ma, mb);
        float m = fmaf(sw[wip][buf][24], y24, xb + ma + mb);
        atomicAdd(&d_agg[dst * DOUT + lane], m);
    }
}

// ---------------- node update (+ pooling on last layer) ----------------------
template <int DIN>
__global__ void k_x(const float* __restrict__ xin_ext, int use_ext,
                    const float* __restrict__ wr, const float* __restrict__ bc,
                    const int* __restrict__ batch, int last) {
    int idx = blockIdx.x * blockDim.x + threadIdx.x;
    if (idx >= NN * DOUT) return;
    int n = idx / DOUT, o = idx % DOUT;
    const float* xin = use_ext ? xin_ext : d_x0;
    float root = __ldg(&bc[o]);
#pragma unroll
    for (int i = 0; i < DIN; i++)
        root = fmaf(xin[(size_t)n * DIN + i], __ldg(&wr[i * DOUT + o]), root);
    float dg = fmaxf(d_deg[n], 1.f);
    float v = d_agg[idx] / dg + root;
    v = (v > 0.f) ? v : expm1f(v);
    if (last) atomicAdd(&d_gsum[batch[n] * DOUT + o], v);
    else      d_x0[idx] = v;
}

// ---------------- final fc ---------------------------------------------------
__global__ void kp_out(const float* __restrict__ wfc, const float* __restrict__ bfc,
                       float* __restrict__ out) {
    int g = threadIdx.x;
    if (g < GG) {
        float c = fmaxf(d_gcnt[g], 1.f);
        float acc = 0.f;
#pragma unroll
        for (int o = 0; o < DOUT; o++)
            acc = fmaf(d_gsum[g * DOUT + o] / c, __ldg(&wfc[o]), acc);
        out[g] = acc + bfc[0];
    }
}

// ---------------- launch -----------------------------------------------------
extern "C" void kernel_launch(void* const* d_in, const int* in_sizes, int n_in,
                              void* d_out, int out_size) {
    (void)in_sizes; (void)n_in; (void)out_size;
    const float* x     = (const float*)d_in[0];
    const float* ea    = (const float*)d_in[1];
    const int*   ei    = (const int*)d_in[2];
    const int*   batch = (const int*)d_in[3];
    const float* w1_0 = (const float*)d_in[4];
    const float* b1_0 = (const float*)d_in[5];
    const float* g_0  = (const float*)d_in[6];
    const float* be_0 = (const float*)d_in[7];
    const float* w2_0 = (const float*)d_in[8];
    const float* b2_0 = (const float*)d_in[9];
    const float* wr_0 = (const float*)d_in[10];
    const float* bc_0 = (const float*)d_in[11];
    const float* w1_1 = (const float*)d_in[12];
    const float* b1_1 = (const float*)d_in[13];
    const float* g_1  = (const float*)d_in[14];
    const float* be_1 = (const float*)d_in[15];
    const float* w2_1 = (const float*)d_in[16];
    const float* b2_1 = (const float*)d_in[17];
    const float* wr_1 = (const float*)d_in[18];
    const float* bc_1 = (const float*)d_in[19];
    const float* wfc  = (const float*)d_in[20];
    const float* bfc  = (const float*)d_in[21];
    float* out = (float*)d_out;

    static cudaStream_t s1 = nullptr, s2 = nullptr;
    static cudaEvent_t ev0, ev1, ev2;
    static void *p_degs, *p_deg, *p_gsum, *p_gcnt, *p_mom;
    if (!s1) {
        cudaStreamCreateWithFlags(&s1, cudaStreamNonBlocking);
        cudaStreamCreateWithFlags(&s2, cudaStreamNonBlocking);
        cudaEventCreateWithFlags(&ev0, cudaEventDisableTiming);
        cudaEventCreateWithFlags(&ev1, cudaEventDisableTiming);
        cudaEventCreateWithFlags(&ev2, cudaEventDisableTiming);
        cudaGetSymbolAddress(&p_degs, d_degs);
        cudaGetSymbolAddress(&p_deg,  d_deg);
        cudaGetSymbolAddress(&p_gsum, d_gsum);
        cudaGetSymbolAddress(&p_gcnt, d_gcnt);
        cudaGetSymbolAddress(&p_mom,  d_mom);
    }

    // fork
    cudaEventRecord(ev0, 0);
    cudaStreamWaitEvent(s1, ev0, 0);
    cudaStreamWaitEvent(s2, ev0, 0);

    // default: CSR prologue (critical path to k_msg)
    cudaMemsetAsync(p_degs, 0, NN * sizeof(int), 0);
    k_deg_src<<<(EE / 4 + 255) / 256, 256>>>(ei);
    k_scan<<<1, 1024>>>();
    k_scatter<<<(EE / 4 + 255) / 256, 256>>>(ei);

    // s1: moments -> BN fold (tiny chain now; no h materialization)
    cudaMemsetAsync(p_mom, 0, 9 * sizeof(double), s1);
    k_mom<<<(EE / 4 + 255) / 256, 256, 0, s1>>>(ea);
    k_bn_both<<<1, 64, 0, s1>>>(g_0, be_0, g_1, be_1, w1_0, b1_0, w1_1, b1_1);
    cudaEventRecord(ev1, s1);

    // s2: dst degree + pool counts + layer-0 y precompute
    cudaMemsetAsync(p_deg,  0, NN * sizeof(float), s2);
    cudaMemsetAsync(p_gsum, 0, GG * DOUT * sizeof(float), s2);
    cudaMemsetAsync(p_gcnt, 0, GG * sizeof(float), s2);
    k_deg_dst<<<(EE / 4 + 255) / 256, 256, 0, s2>>>(ei, batch);
    k_y<16><<<dim3(NX, HID + 1), 128, 0, s2>>>(x, 1, w2_0, b2_0);
    cudaEventRecord(ev2, s2);

    // join
    cudaStreamWaitEvent(0, ev1, 0);
    cudaStreamWaitEvent(0, ev2, 0);

    // layer 0 tail
    k_msg<<<(NN * 32 + 255) / 256, 256>>>(ea, 0);
    k_x<16><<<(NN * DOUT + 255) / 256, 256>>>(x, 1, wr_0, bc_0, batch, 0);

    // layer 1
    k_y<32><<<dim3(NX, HID + 1), 128>>>(nullptr, 0, w2_1, b2_1);
    k_msg<<<(NN * 32 + 255) / 256, 256>>>(ea, 1);
    k_x<32><<<(NN * DOUT + 255) / 256, 256>>>(nullptr, 0, wr_1, bc_1, batch, 1);

    // fc
    kp_out<<<1, 128>>>(wfc, bfc, out);
}